// round 14
// baseline (speedup 1.0000x reference)
#include <cuda_runtime.h>
#include <cuda_fp16.h>
#include <math.h>
#include <stdint.h>

#define BATCH 2
#define SQ    2048
#define DIM   1024
#define NH    16
#define HD    64
#define ROWS  (BATCH * SQ)   // 4096
#define EPSV  1e-5f

#define NFULL 3200           // 3072 qkv + 16 gate + 112 zero pad

// ---------------------------------------------------------------------------
// Scratch (device globals)
// ---------------------------------------------------------------------------
__device__ __half g_xnh[ROWS * DIM];
__device__ __half g_qkvh[ROWS * 3 * DIM];
__device__ __half g_atth[ROWS * DIM];
__device__ float  g_gate[ROWS * NH];
__device__ __half g_wfull[NFULL * DIM];
__device__ __half g_o_wh[DIM * DIM];

// ---------------------------------------------------------------------------
// PTX helpers
// ---------------------------------------------------------------------------
__device__ __forceinline__ void mma_f16(float* d, const uint32_t* a, uint32_t b0, uint32_t b1) {
    asm volatile(
        "mma.sync.aligned.m16n8k16.row.col.f32.f16.f16.f32 "
        "{%0,%1,%2,%3},{%4,%5,%6,%7},{%8,%9},{%0,%1,%2,%3};"
        : "+f"(d[0]), "+f"(d[1]), "+f"(d[2]), "+f"(d[3])
        : "r"(a[0]), "r"(a[1]), "r"(a[2]), "r"(a[3]), "r"(b0), "r"(b1));
}
__device__ __forceinline__ uint32_t h2u(__half2 v) { return *(uint32_t*)&v; }
__device__ __forceinline__ uint32_t smem_u32(const void* p) {
    return (uint32_t)__cvta_generic_to_shared(p);
}
__device__ __forceinline__ uint32_t ex2_h2(uint32_t x) {
    uint32_t r;
    asm("ex2.approx.f16x2 %0, %1;" : "=r"(r) : "r"(x));
    return r;
}

#define LDSM_X4(r0, r1, r2, r3, addr) \
    asm volatile("ldmatrix.sync.aligned.m8n8.x4.shared.b16 {%0,%1,%2,%3},[%4];" \
        : "=r"(r0), "=r"(r1), "=r"(r2), "=r"(r3) : "r"(addr))
#define LDSM_X4T(r0, r1, r2, r3, addr) \
    asm volatile("ldmatrix.sync.aligned.m8n8.x4.trans.shared.b16 {%0,%1,%2,%3},[%4];" \
        : "=r"(r0), "=r"(r1), "=r"(r2), "=r"(r3) : "r"(addr))
#define CP16(smemaddr, gptr) \
    asm volatile("cp.async.cg.shared.global [%0], [%1], 16;" :: "r"(smemaddr), "l"(gptr))
#define CP_COMMIT() asm volatile("cp.async.commit_group;")
#define CP_WAIT0()  asm volatile("cp.async.wait_group 0;")
#define CP_WAIT1()  asm volatile("cp.async.wait_group 1;")

// ---------------------------------------------------------------------------
// 0+1) fused: prenorm RMS (blocks [0,ROWS)) + weight convert (rest)
// ---------------------------------------------------------------------------
#define QKV_WN (3 * DIM * DIM)
#define G_WN   (NH * DIM)
#define WF_N   (NFULL * DIM)
#define O_WN   (DIM * DIM)
#define CV_TOT ((WF_N + O_WN) / 4)
#define CV_BLK ((CV_TOT + 255) / 256)

__global__ __launch_bounds__(256) void pre_conv_kernel(
    const float* __restrict__ x, const float* __restrict__ w, __half* __restrict__ xn,
    const float* __restrict__ qkv_w, const float* __restrict__ gate_w,
    const float* __restrict__ o_w,
    __half* __restrict__ wfull, __half* __restrict__ o_wh)
{
    int t = threadIdx.x;
    if (blockIdx.x < ROWS) {
        int row = blockIdx.x;
        float4 v = *(const float4*)(x + (size_t)row * DIM + t * 4);
        float ss = v.x * v.x + v.y * v.y + v.z * v.z + v.w * v.w;
        #pragma unroll
        for (int o = 16; o > 0; o >>= 1) ss += __shfl_xor_sync(0xffffffffu, ss, o);
        __shared__ float red[8];
        if ((t & 31) == 0) red[t >> 5] = ss;
        __syncthreads();
        float tot = red[0] + red[1] + red[2] + red[3] + red[4] + red[5] + red[6] + red[7];
        float scale = rsqrtf(tot * (1.0f / DIM) + EPSV);
        float4 wv = *(const float4*)(w + t * 4);
        __half2 h0 = __floats2half2_rn(v.x * scale * wv.x, v.y * scale * wv.y);
        __half2 h1 = __floats2half2_rn(v.z * scale * wv.z, v.w * scale * wv.w);
        *(uint2*)(xn + (size_t)row * DIM + t * 4) = make_uint2(h2u(h0), h2u(h1));
    } else {
        int i = ((blockIdx.x - ROWS) * 256 + t) * 4;
        if (i >= WF_N + O_WN) return;
        const float* src;
        __half* dst;
        if (i < QKV_WN)              { src = qkv_w + i;                 dst = wfull + i; }
        else if (i < QKV_WN + G_WN)  { src = gate_w + (i - QKV_WN);     dst = wfull + i; }
        else if (i < WF_N)           { *(uint2*)(wfull + i) = make_uint2(0, 0); return; }
        else                         { src = o_w + (i - WF_N);          dst = o_wh + (i - WF_N); }
        float4 v = *(const float4*)src;
        *(__half2*)(dst)     = __floats2half2_rn(v.x, v.y);
        *(__half2*)(dst + 2) = __floats2half2_rn(v.z, v.w);
    }
}

// ---------------------------------------------------------------------------
// 2) fp16 NT GEMM: 64x128 tile, 128 threads (4 warps of 64x32), BK=32,
//    3-stage cp.async pipeline. 16K regs/CTA -> 4 CTAs/SM: barrier stalls
//    overlap across CTAs.
//    MODE 1: fp32 C + fp32 residual (O proj)
//    MODE 2: QKV fused epilogue — q/k RMS-norm (fp32 accum), gate sigmoid
// ---------------------------------------------------------------------------
#define BKP     40
#define ASTG    5120                  // 64*40*2
#define BSTG    10240                 // 128*40*2
#define GSMEM   (3 * (ASTG + BSTG))   // 46080

template<int MODE>
__global__ __launch_bounds__(128) void hgemm_nt(
    const __half* __restrict__ A, const __half* __restrict__ W,
    const float* __restrict__ R, void* __restrict__ Cv,
    float* __restrict__ gate, const float* __restrict__ qnw,
    const float* __restrict__ knw, int N, int K)
{
    extern __shared__ char dsm[];
    uint32_t sb = smem_u32(dsm);               // A stages [0,3*ASTG), B after
    __shared__ float sred[4][2][8][4];         // [mt][rowhalf][lr][wn]

    int t = threadIdx.x;
    int wn = t >> 5, lane = t & 31;
    int lr = lane >> 2, lq = lane & 3;
    int rA = lane & 15, cSel = lane >> 4;
    int m0 = blockIdx.y * 64, n0 = blockIdx.x * 128;

    // loaders: A row = t>>1, 2 granules at (t&1)*16 halves; B row = t, 4 granules
    int ldrA = t >> 1, ldhA = (t & 1) * 16;
    const __half* Ag = A + (size_t)(m0 + ldrA) * K + ldhA;
    const __half* Bg = W + (size_t)(n0 + t) * K;
    uint32_t aOff = ldrA * (BKP * 2) + ldhA * 2;
    uint32_t bOff = t * (BKP * 2);

    float c[4][4][4];
    #pragma unroll
    for (int mt = 0; mt < 4; mt++)
        #pragma unroll
        for (int nt = 0; nt < 4; nt++)
            #pragma unroll
            for (int i = 0; i < 4; i++) c[mt][nt][i] = 0.f;

    // prologue: chunks 0, 1 -> stages 0, 1
    #pragma unroll
    for (int pc = 0; pc < 2; pc++) {
        uint32_t as = sb + pc * ASTG + aOff;
        uint32_t bs = sb + 3 * ASTG + pc * BSTG + bOff;
        CP16(as, Ag + pc * 32); CP16(as + 16, Ag + pc * 32 + 8);
        const __half* bp = Bg + pc * 32;
        CP16(bs, bp); CP16(bs + 16, bp + 8);
        CP16(bs + 32, bp + 16); CP16(bs + 48, bp + 24);
        CP_COMMIT();
    }

    int nk = K >> 5;
    int stage = 0;
    for (int kt = 0; kt < nk; kt++) {
        CP_WAIT1();
        __syncthreads();

        if (kt + 2 < nk) {
            int ps = (stage + 2) % 3;
            const __half* ap = Ag + (kt + 2) * 32;
            const __half* bp = Bg + (kt + 2) * 32;
            uint32_t as = sb + ps * ASTG + aOff;
            uint32_t bs = sb + 3 * ASTG + ps * BSTG + bOff;
            CP16(as, ap); CP16(as + 16, ap + 8);
            CP16(bs, bp); CP16(bs + 16, bp + 8);
            CP16(bs + 32, bp + 16); CP16(bs + 48, bp + 24);
        }
        CP_COMMIT();

        uint32_t aBase = sb + stage * ASTG;
        uint32_t bBase = sb + 3 * ASTG + stage * BSTG;
        #pragma unroll
        for (int k0 = 0; k0 < 32; k0 += 16) {
            uint32_t a[4][4], bb[2][4];
            #pragma unroll
            for (int mt = 0; mt < 4; mt++) {
                uint32_t addr = aBase + (mt * 16 + rA) * (BKP * 2) + (k0 + cSel * 8) * 2;
                LDSM_X4(a[mt][0], a[mt][1], a[mt][2], a[mt][3], addr);
            }
            #pragma unroll
            for (int np = 0; np < 2; np++) {
                uint32_t addr = bBase + (wn * 32 + np * 16 + rA) * (BKP * 2) + (k0 + cSel * 8) * 2;
                LDSM_X4(bb[np][0], bb[np][1], bb[np][2], bb[np][3], addr);
            }
            #pragma unroll
            for (int mt = 0; mt < 4; mt++)
                #pragma unroll
                for (int nt = 0; nt < 4; nt++) {
                    int np = nt >> 1, od = nt & 1;
                    mma_f16(c[mt][nt], a[mt], bb[np][od], bb[np][od + 2]);
                }
        }
        stage = (stage + 1) % 3;
    }

    if (MODE == 1) {
        #pragma unroll
        for (int mt = 0; mt < 4; mt++) {
            int row = m0 + mt * 16 + lr;
            #pragma unroll
            for (int nt = 0; nt < 4; nt++) {
                int col = n0 + wn * 32 + nt * 8 + 2 * lq;
                float* C = (float*)Cv;
                float2 r0 = *(const float2*)(R + (size_t)row * N + col);
                float2 r1 = *(const float2*)(R + (size_t)(row + 8) * N + col);
                *(float2*)(C + (size_t)row * N + col)       = make_float2(c[mt][nt][0] + r0.x, c[mt][nt][1] + r0.y);
                *(float2*)(C + (size_t)(row + 8) * N + col) = make_float2(c[mt][nt][2] + r1.x, c[mt][nt][3] + r1.y);
            }
        }
    } else if (n0 < 2048) {
        // --- q/k region: fused per-head RMS norm ---
        float ps[4][2];
        #pragma unroll
        for (int mt = 0; mt < 4; mt++) {
            float s0 = 0.f, s1 = 0.f;
            #pragma unroll
            for (int nt = 0; nt < 4; nt++) {
                s0 += c[mt][nt][0] * c[mt][nt][0] + c[mt][nt][1] * c[mt][nt][1];
                s1 += c[mt][nt][2] * c[mt][nt][2] + c[mt][nt][3] * c[mt][nt][3];
            }
            ps[mt][0] = s0; ps[mt][1] = s1;
        }
        #pragma unroll
        for (int mt = 0; mt < 4; mt++)
            #pragma unroll
            for (int hh = 0; hh < 2; hh++) {
                ps[mt][hh] += __shfl_xor_sync(0xffffffffu, ps[mt][hh], 1);
                ps[mt][hh] += __shfl_xor_sync(0xffffffffu, ps[mt][hh], 2);
            }
        if (lq == 0) {
            #pragma unroll
            for (int mt = 0; mt < 4; mt++) {
                sred[mt][0][lr][wn] = ps[mt][0];
                sred[mt][1][lr][wn] = ps[mt][1];
            }
        }
        __syncthreads();

        const float* nw = (n0 < 1024) ? qnw : knw;
        __half* C = (__half*)Cv;
        #pragma unroll
        for (int mt = 0; mt < 4; mt++) {
            int row = m0 + mt * 16 + lr;
            float sum0 = sred[mt][0][lr][wn] + sred[mt][0][lr][wn ^ 1];
            float sum1 = sred[mt][1][lr][wn] + sred[mt][1][lr][wn ^ 1];
            float sc0 = rsqrtf(sum0 * (1.0f / HD) + EPSV);
            float sc1 = rsqrtf(sum1 * (1.0f / HD) + EPSV);
            #pragma unroll
            for (int nt = 0; nt < 4; nt++) {
                int col = n0 + wn * 32 + nt * 8 + 2 * lq;
                int cih = (wn & 1) * 32 + nt * 8 + 2 * lq;
                float w0 = nw[cih], w1 = nw[cih + 1];
                *(__half2*)(C + (size_t)row * (3 * DIM) + col) =
                    __floats2half2_rn(c[mt][nt][0] * sc0 * w0, c[mt][nt][1] * sc0 * w1);
                *(__half2*)(C + (size_t)(row + 8) * (3 * DIM) + col) =
                    __floats2half2_rn(c[mt][nt][2] * sc1 * w0, c[mt][nt][3] * sc1 * w1);
            }
        }
    } else {
        // --- v / gate / pad region ---
        #pragma unroll
        for (int mt = 0; mt < 4; mt++) {
            int row = m0 + mt * 16 + lr;
            #pragma unroll
            for (int nt = 0; nt < 4; nt++) {
                int col = n0 + wn * 32 + nt * 8 + 2 * lq;
                if (col < 3 * DIM) {
                    __half* C = (__half*)Cv;
                    *(__half2*)(C + (size_t)row * (3 * DIM) + col)       = __floats2half2_rn(c[mt][nt][0], c[mt][nt][1]);
                    *(__half2*)(C + (size_t)(row + 8) * (3 * DIM) + col) = __floats2half2_rn(c[mt][nt][2], c[mt][nt][3]);
                } else if (col < 3 * DIM + NH) {
                    int gc = col - 3 * DIM;
                    gate[(size_t)row * NH + gc]           = 1.f / (1.f + __expf(-c[mt][nt][0]));
                    gate[(size_t)row * NH + gc + 1]       = 1.f / (1.f + __expf(-c[mt][nt][1]));
                    gate[(size_t)(row + 8) * NH + gc]     = 1.f / (1.f + __expf(-c[mt][nt][2]));
                    gate[(size_t)(row + 8) * NH + gc + 1] = 1.f / (1.f + __expf(-c[mt][nt][3]));
                }
            }
        }
    }
}

// ---------------------------------------------------------------------------
// 3) attention: 256 q-rows/block, 8 warps x 32 rows, 3-stage cp.async (R13)
// ---------------------------------------------------------------------------
#define KVP   72
#define KVSTG (64 * KVP * 2)
#define ASMEM (6 * KVSTG)

__global__ __launch_bounds__(256, 1) void attn_f16(
    const __half* __restrict__ qkv, const float* __restrict__ sg, __half* __restrict__ att)
{
    extern __shared__ char dsm[];
    uint32_t sb = smem_u32(dsm);

    int qb = blockIdx.x, h = blockIdx.y, b = blockIdx.z;
    int t = threadIdx.x, warp = t >> 5, lane = t & 31;
    int lr = lane >> 2, lq = lane & 3;
    int rA = lane & 15, cSel = lane >> 4;
    int g8 = lane >> 3, w8 = lane & 7;
    int tRow = (g8 & 1) * 8 + w8, tCol = (g8 >> 1) * 8;

    uint32_t bOnes = (lane < 4) ? 0x3C003C00u : 0u;

    uint32_t aQ[2][4][4];
    #pragma unroll
    for (int g = 0; g < 2; g++) {
        int r0 = qb * 256 + warp * 32 + g * 16 + lr;
        const __half* Qp  = qkv + ((size_t)(b * SQ) + r0) * (3 * DIM) + h * HD;
        const __half* Qp8 = Qp + 8 * (3 * DIM);
        __half2 s8 = __floats2half2_rn(0.1803368801f, 0.1803368801f);
        #pragma unroll
        for (int dt = 0; dt < 4; dt++) {
            aQ[g][dt][0] = h2u(__hmul2(*(const __half2*)(Qp  + dt * 16 + 2 * lq), s8));
            aQ[g][dt][1] = h2u(__hmul2(*(const __half2*)(Qp8 + dt * 16 + 2 * lq), s8));
            aQ[g][dt][2] = h2u(__hmul2(*(const __half2*)(Qp  + dt * 16 + 8 + 2 * lq), s8));
            aQ[g][dt][3] = h2u(__hmul2(*(const __half2*)(Qp8 + dt * 16 + 8 + 2 * lq), s8));
        }
    }

    float o[2][8][4], lacc[2][4], m0[2], m1[2];
    #pragma unroll
    for (int g = 0; g < 2; g++) {
        #pragma unroll
        for (int nt = 0; nt < 8; nt++)
            #pragma unroll
            for (int i = 0; i < 4; i++) o[g][nt][i] = 0.f;
        #pragma unroll
        for (int i = 0; i < 4; i++) lacc[g][i] = 0.f;
        m0[g] = -1e30f; m1[g] = -1e30f;
    }

    int lkey = t & 63, lseg = (t >> 6) * 16;
    const __half* Kg = qkv + ((size_t)(b * SQ) + lkey) * (3 * DIM) + DIM + h * HD + lseg;
    const __half* Vg = Kg + DIM;
    uint32_t kvOff = lkey * (KVP * 2) + lseg * 2;

    #pragma unroll
    for (int pc = 0; pc < 2; pc++) {
        const __half* kg = Kg + (size_t)pc * 64 * (3 * DIM);
        const __half* vg = Vg + (size_t)pc * 64 * (3 * DIM);
        uint32_t ks = sb + pc * KVSTG + kvOff;
        uint32_t vs = sb + (3 + pc) * KVSTG + kvOff;
        CP16(ks, kg); CP16(ks + 16, kg + 8);
        CP16(vs, vg); CP16(vs + 16, vg + 8);
        CP_COMMIT();
    }

    int ntiles = SQ / 64;
    int stage = 0;
    for (int it = 0; it < ntiles; it++) {
        CP_WAIT1();
        __syncthreads();

        if (it + 2 < ntiles) {
            int ps = (stage + 2) % 3;
            const __half* kg = Kg + (size_t)(it + 2) * 64 * (3 * DIM);
            const __half* vg = Vg + (size_t)(it + 2) * 64 * (3 * DIM);
            uint32_t ks = sb + ps * KVSTG + kvOff;
            uint32_t vs = sb + (3 + ps) * KVSTG + kvOff;
            CP16(ks, kg); CP16(ks + 16, kg + 8);
            CP16(vs, vg); CP16(vs + 16, vg + 8);
        }
        CP_COMMIT();

        uint32_t kBase = sb + stage * KVSTG;
        uint32_t vBase = sb + (3 + stage) * KVSTG;

        float sc[2][8][4];
        #pragma unroll
        for (int g = 0; g < 2; g++)
            #pragma unroll
            for (int nt = 0; nt < 8; nt++)
                #pragma unroll
                for (int i = 0; i < 4; i++) sc[g][nt][i] = 0.f;

        #pragma unroll
        for (int dt = 0; dt < 4; dt++) {
            #pragma unroll
            for (int kb = 0; kb < 4; kb++) {
                uint32_t r0, r1, r2, r3;
                uint32_t addr = kBase + (kb * 16 + rA) * (KVP * 2) + (dt * 16 + cSel * 8) * 2;
                LDSM_X4(r0, r1, r2, r3, addr);
                #pragma unroll
                for (int g = 0; g < 2; g++) {
                    mma_f16(sc[g][2 * kb],     aQ[g][dt], r0, r2);
                    mma_f16(sc[g][2 * kb + 1], aQ[g][dt], r1, r3);
                }
            }
        }

        uint32_t pl[2][8], ph[2][8];
        #pragma unroll
        for (int g = 0; g < 2; g++) {
            float rm0 = sc[g][0][0], rm1 = sc[g][0][2];
            #pragma unroll
            for (int nt = 0; nt < 8; nt++) {
                rm0 = fmaxf(rm0, fmaxf(sc[g][nt][0], sc[g][nt][1]));
                rm1 = fmaxf(rm1, fmaxf(sc[g][nt][2], sc[g][nt][3]));
            }
            rm0 = fmaxf(rm0, __shfl_xor_sync(0xffffffffu, rm0, 1));
            rm0 = fmaxf(rm0, __shfl_xor_sync(0xffffffffu, rm0, 2));
            rm1 = fmaxf(rm1, __shfl_xor_sync(0xffffffffu, rm1, 1));
            rm1 = fmaxf(rm1, __shfl_xor_sync(0xffffffffu, rm1, 2));
            float mn0 = fmaxf(m0[g], rm0), mn1 = fmaxf(m1[g], rm1);
            float co0 = exp2f(m0[g] - mn0), co1 = exp2f(m1[g] - mn1);
            m0[g] = mn0; m1[g] = mn1;

            __half2 mh0 = __floats2half2_rn(mn0, mn0);
            __half2 mh1 = __floats2half2_rn(mn1, mn1);
            #pragma unroll
            for (int nt = 0; nt < 8; nt++) {
                pl[g][nt] = ex2_h2(h2u(__hsub2(__floats2half2_rn(sc[g][nt][0], sc[g][nt][1]), mh0)));
                ph[g][nt] = ex2_h2(h2u(__hsub2(__floats2half2_rn(sc[g][nt][2], sc[g][nt][3]), mh1)));
            }
            #pragma unroll
            for (int nt = 0; nt < 8; nt++) {
                o[g][nt][0] *= co0; o[g][nt][1] *= co0;
                o[g][nt][2] *= co1; o[g][nt][3] *= co1;
            }
            lacc[g][0] *= co0; lacc[g][1] *= co0;
            lacc[g][2] *= co1; lacc[g][3] *= co1;
        }

        #pragma unroll
        for (int kt = 0; kt < 4; kt++) {
            uint32_t aP[2][4];
            #pragma unroll
            for (int g = 0; g < 2; g++) {
                aP[g][0] = pl[g][2 * kt];     aP[g][1] = ph[g][2 * kt];
                aP[g][2] = pl[g][2 * kt + 1]; aP[g][3] = ph[g][2 * kt + 1];
                mma_f16(lacc[g], aP[g], bOnes, bOnes);
            }
            #pragma unroll
            for (int dp = 0; dp < 4; dp++) {
                uint32_t r0, r1, r2, r3;
                uint32_t addr = vBase + (kt * 16 + tRow) * (KVP * 2) + (dp * 16 + tCol) * 2;
                LDSM_X4T(r0, r1, r2, r3, addr);
                #pragma unroll
                for (int g = 0; g < 2; g++) {
                    mma_f16(o[g][2 * dp],     aP[g], r0, r1);
                    mma_f16(o[g][2 * dp + 1], aP[g], r2, r3);
                }
            }
        }
        stage = (stage + 1) % 3;
    }

    #pragma unroll
    for (int g = 0; g < 2; g++) {
        float l0 = __shfl_sync(0xffffffffu, lacc[g][0], lane & 28);
        float l1 = __shfl_sync(0xffffffffu, lacc[g][2], lane & 28);
        int r0 = qb * 256 + warp * 32 + g * 16 + lr;
        int r1 = r0 + 8;
        float g0 = sg[((size_t)(b * SQ) + r0) * NH + h];
        float g1 = sg[((size_t)(b * SQ) + r1) * NH + h];
        float f0 = g0 / l0, f1 = g1 / l1;
        __half* o0 = att + ((size_t)(b * SQ) + r0) * DIM + h * HD;
        __half* o1 = att + ((size_t)(b * SQ) + r1) * DIM + h * HD;
        #pragma unroll
        for (int nt = 0; nt < 8; nt++) {
            int col = nt * 8 + 2 * lq;
            *(__half2*)(o0 + col) = __floats2half2_rn(o[g][nt][0] * f0, o[g][nt][1] * f0);
            *(__half2*)(o1 + col) = __floats2half2_rn(o[g][nt][2] * f1, o[g][nt][3] * f1);
        }
    }
}

// ---------------------------------------------------------------------------
// launch
// ---------------------------------------------------------------------------
extern "C" void kernel_launch(void* const* d_in, const int* in_sizes, int n_in,
                              void* d_out, int out_size)
{
    const float* x         = (const float*)d_in[0];
    const float* prenorm_w = (const float*)d_in[1];
    const float* qkv_w     = (const float*)d_in[2];
    const float* gate_w    = (const float*)d_in[3];
    const float* o_w       = (const float*)d_in[4];
    const float* q_norm_w  = (const float*)d_in[5];
    const float* k_norm_w  = (const float*)d_in[6];
    float* out = (float*)d_out;

    __half *p_xnh, *p_qkvh, *p_atth, *p_wfull, *p_o_wh;
    float *p_gate;
    cudaGetSymbolAddress((void**)&p_xnh,   g_xnh);
    cudaGetSymbolAddress((void**)&p_qkvh,  g_qkvh);
    cudaGetSymbolAddress((void**)&p_atth,  g_atth);
    cudaGetSymbolAddress((void**)&p_gate,  g_gate);
    cudaGetSymbolAddress((void**)&p_wfull, g_wfull);
    cudaGetSymbolAddress((void**)&p_o_wh,  g_o_wh);

    cudaFuncSetAttribute(hgemm_nt<1>, cudaFuncAttributeMaxDynamicSharedMemorySize, GSMEM);
    cudaFuncSetAttribute(hgemm_nt<2>, cudaFuncAttributeMaxDynamicSharedMemorySize, GSMEM);
    cudaFuncSetAttribute(attn_f16,    cudaFuncAttributeMaxDynamicSharedMemorySize, ASMEM);

    // 0+1) prenorm + weight convert (fused)
    pre_conv_kernel<<<ROWS + CV_BLK, 256>>>(
        x, prenorm_w, p_xnh, qkv_w, gate_w, o_w, p_wfull, p_o_wh);

    // 2) QKV + gate + q/k-norm fused GEMM: [4096,1024] x [3200,1024]^T
    hgemm_nt<2><<<dim3(NFULL / 128, ROWS / 64), 128, GSMEM>>>(
        p_xnh, p_wfull, nullptr, p_qkvh, p_gate, q_norm_w, k_norm_w, NFULL, DIM);

    // 3) attention: 256 q-rows per CTA, 3-stage pipeline
    attn_f16<<<dim3(SQ / 256, NH, BATCH), 256, ASMEM>>>(p_qkvh, p_gate, p_atth);

    // 4) O GEMM + residual
    hgemm_nt<1><<<dim3(DIM / 128, ROWS / 64), 128, GSMEM>>>(
        p_atth, p_o_wh, x, out, nullptr, nullptr, nullptr, DIM, DIM);
}

// round 15
// speedup vs baseline: 1.1995x; 1.1995x over previous
#include <cuda_runtime.h>
#include <cuda_fp16.h>
#include <math.h>
#include <stdint.h>

#define BATCH 2
#define SQ    2048
#define DIM   1024
#define NH    16
#define HD    64
#define ROWS  (BATCH * SQ)   // 4096
#define EPSV  1e-5f

#define NFULL 3200           // 3072 qkv + 16 gate + 112 zero pad

// ---------------------------------------------------------------------------
// Scratch (device globals)
// ---------------------------------------------------------------------------
__device__ __half g_xnh[ROWS * DIM];
__device__ __half g_qkvh[ROWS * 3 * DIM];
__device__ __half g_atth[ROWS * DIM];
__device__ float  g_gate[ROWS * NH];
__device__ __half g_wfull[NFULL * DIM];
__device__ __half g_o_wh[DIM * DIM];

// ---------------------------------------------------------------------------
// PTX helpers
// ---------------------------------------------------------------------------
__device__ __forceinline__ void mma_f16(float* d, const uint32_t* a, uint32_t b0, uint32_t b1) {
    asm volatile(
        "mma.sync.aligned.m16n8k16.row.col.f32.f16.f16.f32 "
        "{%0,%1,%2,%3},{%4,%5,%6,%7},{%8,%9},{%0,%1,%2,%3};"
        : "+f"(d[0]), "+f"(d[1]), "+f"(d[2]), "+f"(d[3])
        : "r"(a[0]), "r"(a[1]), "r"(a[2]), "r"(a[3]), "r"(b0), "r"(b1));
}
__device__ __forceinline__ uint32_t h2u(__half2 v) { return *(uint32_t*)&v; }
__device__ __forceinline__ uint32_t smem_u32(const void* p) {
    return (uint32_t)__cvta_generic_to_shared(p);
}
__device__ __forceinline__ uint32_t ex2_h2(uint32_t x) {
    uint32_t r;
    asm("ex2.approx.f16x2 %0, %1;" : "=r"(r) : "r"(x));
    return r;
}

#define LDSM_X4(r0, r1, r2, r3, addr) \
    asm volatile("ldmatrix.sync.aligned.m8n8.x4.shared.b16 {%0,%1,%2,%3},[%4];" \
        : "=r"(r0), "=r"(r1), "=r"(r2), "=r"(r3) : "r"(addr))
#define LDSM_X4T(r0, r1, r2, r3, addr) \
    asm volatile("ldmatrix.sync.aligned.m8n8.x4.trans.shared.b16 {%0,%1,%2,%3},[%4];" \
        : "=r"(r0), "=r"(r1), "=r"(r2), "=r"(r3) : "r"(addr))
#define CP16(smemaddr, gptr) \
    asm volatile("cp.async.cg.shared.global [%0], [%1], 16;" :: "r"(smemaddr), "l"(gptr))
#define CP_COMMIT() asm volatile("cp.async.commit_group;")
#define CP_WAIT2()  asm volatile("cp.async.wait_group 2;")

// ---------------------------------------------------------------------------
// 0+1) fused: prenorm RMS (blocks [0,ROWS)) + weight convert (rest)
// ---------------------------------------------------------------------------
#define QKV_WN (3 * DIM * DIM)
#define G_WN   (NH * DIM)
#define WF_N   (NFULL * DIM)
#define O_WN   (DIM * DIM)
#define CV_TOT ((WF_N + O_WN) / 4)
#define CV_BLK ((CV_TOT + 255) / 256)

__global__ __launch_bounds__(256) void pre_conv_kernel(
    const float* __restrict__ x, const float* __restrict__ w, __half* __restrict__ xn,
    const float* __restrict__ qkv_w, const float* __restrict__ gate_w,
    const float* __restrict__ o_w,
    __half* __restrict__ wfull, __half* __restrict__ o_wh)
{
    int t = threadIdx.x;
    if (blockIdx.x < ROWS) {
        int row = blockIdx.x;
        float4 v = *(const float4*)(x + (size_t)row * DIM + t * 4);
        float ss = v.x * v.x + v.y * v.y + v.z * v.z + v.w * v.w;
        #pragma unroll
        for (int o = 16; o > 0; o >>= 1) ss += __shfl_xor_sync(0xffffffffu, ss, o);
        __shared__ float red[8];
        if ((t & 31) == 0) red[t >> 5] = ss;
        __syncthreads();
        float tot = red[0] + red[1] + red[2] + red[3] + red[4] + red[5] + red[6] + red[7];
        float scale = rsqrtf(tot * (1.0f / DIM) + EPSV);
        float4 wv = *(const float4*)(w + t * 4);
        __half2 h0 = __floats2half2_rn(v.x * scale * wv.x, v.y * scale * wv.y);
        __half2 h1 = __floats2half2_rn(v.z * scale * wv.z, v.w * scale * wv.w);
        *(uint2*)(xn + (size_t)row * DIM + t * 4) = make_uint2(h2u(h0), h2u(h1));
    } else {
        int i = ((blockIdx.x - ROWS) * 256 + t) * 4;
        if (i >= WF_N + O_WN) return;
        const float* src;
        __half* dst;
        if (i < QKV_WN)              { src = qkv_w + i;                 dst = wfull + i; }
        else if (i < QKV_WN + G_WN)  { src = gate_w + (i - QKV_WN);     dst = wfull + i; }
        else if (i < WF_N)           { *(uint2*)(wfull + i) = make_uint2(0, 0); return; }
        else                         { src = o_w + (i - WF_N);          dst = o_wh + (i - WF_N); }
        float4 v = *(const float4*)src;
        *(__half2*)(dst)     = __floats2half2_rn(v.x, v.y);
        *(__half2*)(dst + 2) = __floats2half2_rn(v.z, v.w);
    }
}

// ---------------------------------------------------------------------------
// 2) fp16 NT GEMM: 128x128 tile, BK=32, 4-stage cp.async pipeline
//    (wait_group 2: chunk consumed at kt was issued at kt-3)
//    MODE 1: fp32 C + fp32 residual (O proj)
//    MODE 2: QKV fused epilogue — q/k RMS-norm (fp32 accum), gate sigmoid
// ---------------------------------------------------------------------------
#define BKP    40
#define STGB   10240                 // bytes per stage per array (128*40*2)
#define GSMEM  (8 * STGB)            // 4 A stages + 4 B stages = 81920

template<int MODE>
__global__ __launch_bounds__(256) void hgemm_nt(
    const __half* __restrict__ A, const __half* __restrict__ W,
    const float* __restrict__ R, void* __restrict__ Cv,
    float* __restrict__ gate, const float* __restrict__ qnw,
    const float* __restrict__ knw, int N, int K)
{
    extern __shared__ char dsm[];
    uint32_t sb = smem_u32(dsm);               // A stages at sb, B at sb+4*STGB
    __shared__ float sred[2][4][2][8][4];

    int t = threadIdx.x;
    int warp = t >> 5, lane = t & 31;
    int wm = warp & 1, wn = warp >> 1;
    int lr = lane >> 2, lq = lane & 3;
    int rA = lane & 15, cSel = lane >> 4;
    int m0 = blockIdx.y * 128, n0 = blockIdx.x * 128;

    int ldr = t >> 1, ldh = (t & 1) * 16;
    const __half* Ag = A + (size_t)(m0 + ldr) * K + ldh;
    const __half* Bg = W + (size_t)(n0 + ldr) * K + ldh;
    uint32_t sOff = ldr * (BKP * 2) + ldh * 2;

    float c[4][4][4];
    #pragma unroll
    for (int mt = 0; mt < 4; mt++)
        #pragma unroll
        for (int nt = 0; nt < 4; nt++)
            #pragma unroll
            for (int i = 0; i < 4; i++) c[mt][nt][i] = 0.f;

    // prologue: chunks 0..2 -> stages 0..2
    #pragma unroll
    for (int pc = 0; pc < 3; pc++) {
        uint32_t as = sb + pc * STGB + sOff;
        uint32_t bs = sb + (4 + pc) * STGB + sOff;
        CP16(as, Ag + pc * 32); CP16(as + 16, Ag + pc * 32 + 8);
        CP16(bs, Bg + pc * 32); CP16(bs + 16, Bg + pc * 32 + 8);
        CP_COMMIT();
    }

    int nk = K >> 5;
    int stage = 0;
    for (int kt = 0; kt < nk; kt++) {
        CP_WAIT2();          // chunk kt (issued at kt-3) has landed
        __syncthreads();     // all warps done with stage (kt+3)%4 (read at kt-1)

        if (kt + 3 < nk) {
            int ps = (stage + 3) & 3;
            const __half* ap = Ag + (kt + 3) * 32;
            const __half* bp = Bg + (kt + 3) * 32;
            uint32_t as = sb + ps * STGB + sOff;
            uint32_t bs = sb + (4 + ps) * STGB + sOff;
            CP16(as, ap); CP16(as + 16, ap + 8);
            CP16(bs, bp); CP16(bs + 16, bp + 8);
        }
        CP_COMMIT();         // unconditional: preserves pending-group invariant

        uint32_t aBase = sb + stage * STGB;
        uint32_t bBase = sb + (4 + stage) * STGB;
        #pragma unroll
        for (int k0 = 0; k0 < 32; k0 += 16) {
            uint32_t a[4][4], bb[2][4];
            #pragma unroll
            for (int mt = 0; mt < 4; mt++) {
                uint32_t addr = aBase + (wm * 64 + mt * 16 + rA) * (BKP * 2) + (k0 + cSel * 8) * 2;
                LDSM_X4(a[mt][0], a[mt][1], a[mt][2], a[mt][3], addr);
            }
            #pragma unroll
            for (int np = 0; np < 2; np++) {
                uint32_t addr = bBase + (wn * 32 + np * 16 + rA) * (BKP * 2) + (k0 + cSel * 8) * 2;
                LDSM_X4(bb[np][0], bb[np][1], bb[np][2], bb[np][3], addr);
            }
            #pragma unroll
            for (int mt = 0; mt < 4; mt++)
                #pragma unroll
                for (int nt = 0; nt < 4; nt++) {
                    int np = nt >> 1, od = nt & 1;
                    mma_f16(c[mt][nt], a[mt], bb[np][od], bb[np][od + 2]);
                }
        }
        stage = (stage + 1) & 3;
    }

    if (MODE == 1) {
        #pragma unroll
        for (int mt = 0; mt < 4; mt++) {
            int row = m0 + wm * 64 + mt * 16 + lr;
            #pragma unroll
            for (int nt = 0; nt < 4; nt++) {
                int col = n0 + wn * 32 + nt * 8 + 2 * lq;
                float* C = (float*)Cv;
                float2 r0 = *(const float2*)(R + (size_t)row * N + col);
                float2 r1 = *(const float2*)(R + (size_t)(row + 8) * N + col);
                *(float2*)(C + (size_t)row * N + col)       = make_float2(c[mt][nt][0] + r0.x, c[mt][nt][1] + r0.y);
                *(float2*)(C + (size_t)(row + 8) * N + col) = make_float2(c[mt][nt][2] + r1.x, c[mt][nt][3] + r1.y);
            }
        }
    } else if (n0 < 2048) {
        float ps[4][2];
        #pragma unroll
        for (int mt = 0; mt < 4; mt++) {
            float s0 = 0.f, s1 = 0.f;
            #pragma unroll
            for (int nt = 0; nt < 4; nt++) {
                s0 += c[mt][nt][0] * c[mt][nt][0] + c[mt][nt][1] * c[mt][nt][1];
                s1 += c[mt][nt][2] * c[mt][nt][2] + c[mt][nt][3] * c[mt][nt][3];
            }
            ps[mt][0] = s0; ps[mt][1] = s1;
        }
        #pragma unroll
        for (int mt = 0; mt < 4; mt++)
            #pragma unroll
            for (int hh = 0; hh < 2; hh++) {
                ps[mt][hh] += __shfl_xor_sync(0xffffffffu, ps[mt][hh], 1);
                ps[mt][hh] += __shfl_xor_sync(0xffffffffu, ps[mt][hh], 2);
            }
        if (lq == 0) {
            #pragma unroll
            for (int mt = 0; mt < 4; mt++) {
                sred[wm][mt][0][lr][wn] = ps[mt][0];
                sred[wm][mt][1][lr][wn] = ps[mt][1];
            }
        }
        __syncthreads();

        const float* nw = (n0 < 1024) ? qnw : knw;
        __half* C = (__half*)Cv;
        #pragma unroll
        for (int mt = 0; mt < 4; mt++) {
            int row = m0 + wm * 64 + mt * 16 + lr;
            float sum0 = sred[wm][mt][0][lr][wn] + sred[wm][mt][0][lr][wn ^ 1];
            float sum1 = sred[wm][mt][1][lr][wn] + sred[wm][mt][1][lr][wn ^ 1];
            float sc0 = rsqrtf(sum0 * (1.0f / HD) + EPSV);
            float sc1 = rsqrtf(sum1 * (1.0f / HD) + EPSV);
            #pragma unroll
            for (int nt = 0; nt < 4; nt++) {
                int col = n0 + wn * 32 + nt * 8 + 2 * lq;
                int cih = (wn & 1) * 32 + nt * 8 + 2 * lq;
                float w0 = nw[cih], w1 = nw[cih + 1];
                *(__half2*)(C + (size_t)row * (3 * DIM) + col) =
                    __floats2half2_rn(c[mt][nt][0] * sc0 * w0, c[mt][nt][1] * sc0 * w1);
                *(__half2*)(C + (size_t)(row + 8) * (3 * DIM) + col) =
                    __floats2half2_rn(c[mt][nt][2] * sc1 * w0, c[mt][nt][3] * sc1 * w1);
            }
        }
    } else {
        #pragma unroll
        for (int mt = 0; mt < 4; mt++) {
            int row = m0 + wm * 64 + mt * 16 + lr;
            #pragma unroll
            for (int nt = 0; nt < 4; nt++) {
                int col = n0 + wn * 32 + nt * 8 + 2 * lq;
                if (col < 3 * DIM) {
                    __half* C = (__half*)Cv;
                    *(__half2*)(C + (size_t)row * (3 * DIM) + col)       = __floats2half2_rn(c[mt][nt][0], c[mt][nt][1]);
                    *(__half2*)(C + (size_t)(row + 8) * (3 * DIM) + col) = __floats2half2_rn(c[mt][nt][2], c[mt][nt][3]);
                } else if (col < 3 * DIM + NH) {
                    int gc = col - 3 * DIM;
                    gate[(size_t)row * NH + gc]           = 1.f / (1.f + __expf(-c[mt][nt][0]));
                    gate[(size_t)row * NH + gc + 1]       = 1.f / (1.f + __expf(-c[mt][nt][1]));
                    gate[(size_t)(row + 8) * NH + gc]     = 1.f / (1.f + __expf(-c[mt][nt][2]));
                    gate[(size_t)(row + 8) * NH + gc + 1] = 1.f / (1.f + __expf(-c[mt][nt][3]));
                }
            }
        }
    }
}

// ---------------------------------------------------------------------------
// 3) attention: 256 q-rows/block, 8 warps x 32 rows, 4-stage cp.async
//    pipeline (wait_group 2) over 64-key tiles.
// ---------------------------------------------------------------------------
#define KVP   72
#define KVSTG (64 * KVP * 2)          // 9216 B per stage per array
#define ASMEM (8 * KVSTG)             // 4 K stages + 4 V stages = 73728

__global__ __launch_bounds__(256, 1) void attn_f16(
    const __half* __restrict__ qkv, const float* __restrict__ sg, __half* __restrict__ att)
{
    extern __shared__ char dsm[];
    uint32_t sb = smem_u32(dsm);      // K stages at sb, V at sb + 4*KVSTG

    int qb = blockIdx.x, h = blockIdx.y, b = blockIdx.z;
    int t = threadIdx.x, warp = t >> 5, lane = t & 31;
    int lr = lane >> 2, lq = lane & 3;
    int rA = lane & 15, cSel = lane >> 4;
    int g8 = lane >> 3, w8 = lane & 7;
    int tRow = (g8 & 1) * 8 + w8, tCol = (g8 >> 1) * 8;

    uint32_t bOnes = (lane < 4) ? 0x3C003C00u : 0u;

    uint32_t aQ[2][4][4];
    #pragma unroll
    for (int g = 0; g < 2; g++) {
        int r0 = qb * 256 + warp * 32 + g * 16 + lr;
        const __half* Qp  = qkv + ((size_t)(b * SQ) + r0) * (3 * DIM) + h * HD;
        const __half* Qp8 = Qp + 8 * (3 * DIM);
        __half2 s8 = __floats2half2_rn(0.1803368801f, 0.1803368801f);
        #pragma unroll
        for (int dt = 0; dt < 4; dt++) {
            aQ[g][dt][0] = h2u(__hmul2(*(const __half2*)(Qp  + dt * 16 + 2 * lq), s8));
            aQ[g][dt][1] = h2u(__hmul2(*(const __half2*)(Qp8 + dt * 16 + 2 * lq), s8));
            aQ[g][dt][2] = h2u(__hmul2(*(const __half2*)(Qp  + dt * 16 + 8 + 2 * lq), s8));
            aQ[g][dt][3] = h2u(__hmul2(*(const __half2*)(Qp8 + dt * 16 + 8 + 2 * lq), s8));
        }
    }

    float o[2][8][4], lacc[2][4], m0[2], m1[2];
    #pragma unroll
    for (int g = 0; g < 2; g++) {
        #pragma unroll
        for (int nt = 0; nt < 8; nt++)
            #pragma unroll
            for (int i = 0; i < 4; i++) o[g][nt][i] = 0.f;
        #pragma unroll
        for (int i = 0; i < 4; i++) lacc[g][i] = 0.f;
        m0[g] = -1e30f; m1[g] = -1e30f;
    }

    int lkey = t & 63, lseg = (t >> 6) * 16;
    const __half* Kg = qkv + ((size_t)(b * SQ) + lkey) * (3 * DIM) + DIM + h * HD + lseg;
    const __half* Vg = Kg + DIM;
    uint32_t kvOff = lkey * (KVP * 2) + lseg * 2;

    // prologue: tiles 0..2 -> stages 0..2
    #pragma unroll
    for (int pc = 0; pc < 3; pc++) {
        const __half* kg = Kg + (size_t)pc * 64 * (3 * DIM);
        const __half* vg = Vg + (size_t)pc * 64 * (3 * DIM);
        uint32_t ks = sb + pc * KVSTG + kvOff;
        uint32_t vs = sb + (4 + pc) * KVSTG + kvOff;
        CP16(ks, kg); CP16(ks + 16, kg + 8);
        CP16(vs, vg); CP16(vs + 16, vg + 8);
        CP_COMMIT();
    }

    int ntiles = SQ / 64;
    int stage = 0;
    for (int it = 0; it < ntiles; it++) {
        CP_WAIT2();          // tile `it` (issued at it-3) has landed
        __syncthreads();     // all warps done with stage (it+3)%4 (read at it-1)

        if (it + 3 < ntiles) {
            int ps = (stage + 3) & 3;
            const __half* kg = Kg + (size_t)(it + 3) * 64 * (3 * DIM);
            const __half* vg = Vg + (size_t)(it + 3) * 64 * (3 * DIM);
            uint32_t ks = sb + ps * KVSTG + kvOff;
            uint32_t vs = sb + (4 + ps) * KVSTG + kvOff;
            CP16(ks, kg); CP16(ks + 16, kg + 8);
            CP16(vs, vg); CP16(vs + 16, vg + 8);
        }
        CP_COMMIT();

        uint32_t kBase = sb + stage * KVSTG;
        uint32_t vBase = sb + (4 + stage) * KVSTG;

        float sc[2][8][4];
        #pragma unroll
        for (int g = 0; g < 2; g++)
            #pragma unroll
            for (int nt = 0; nt < 8; nt++)
                #pragma unroll
                for (int i = 0; i < 4; i++) sc[g][nt][i] = 0.f;

        #pragma unroll
        for (int dt = 0; dt < 4; dt++) {
            #pragma unroll
            for (int kb = 0; kb < 4; kb++) {
                uint32_t r0, r1, r2, r3;
                uint32_t addr = kBase + (kb * 16 + rA) * (KVP * 2) + (dt * 16 + cSel * 8) * 2;
                LDSM_X4(r0, r1, r2, r3, addr);
                #pragma unroll
                for (int g = 0; g < 2; g++) {
                    mma_f16(sc[g][2 * kb],     aQ[g][dt], r0, r2);
                    mma_f16(sc[g][2 * kb + 1], aQ[g][dt], r1, r3);
                }
            }
        }

        uint32_t pl[2][8], ph[2][8];
        #pragma unroll
        for (int g = 0; g < 2; g++) {
            float rm0 = sc[g][0][0], rm1 = sc[g][0][2];
            #pragma unroll
            for (int nt = 0; nt < 8; nt++) {
                rm0 = fmaxf(rm0, fmaxf(sc[g][nt][0], sc[g][nt][1]));
                rm1 = fmaxf(rm1, fmaxf(sc[g][nt][2], sc[g][nt][3]));
            }
            rm0 = fmaxf(rm0, __shfl_xor_sync(0xffffffffu, rm0, 1));
            rm0 = fmaxf(rm0, __shfl_xor_sync(0xffffffffu, rm0, 2));
            rm1 = fmaxf(rm1, __shfl_xor_sync(0xffffffffu, rm1, 1));
            rm1 = fmaxf(rm1, __shfl_xor_sync(0xffffffffu, rm1, 2));
            float mn0 = fmaxf(m0[g], rm0), mn1 = fmaxf(m1[g], rm1);
            float co0 = exp2f(m0[g] - mn0), co1 = exp2f(m1[g] - mn1);
            m0[g] = mn0; m1[g] = mn1;

            __half2 mh0 = __floats2half2_rn(mn0, mn0);
            __half2 mh1 = __floats2half2_rn(mn1, mn1);
            #pragma unroll
            for (int nt = 0; nt < 8; nt++) {
                pl[g][nt] = ex2_h2(h2u(__hsub2(__floats2half2_rn(sc[g][nt][0], sc[g][nt][1]), mh0)));
                ph[g][nt] = ex2_h2(h2u(__hsub2(__floats2half2_rn(sc[g][nt][2], sc[g][nt][3]), mh1)));
            }
            #pragma unroll
            for (int nt = 0; nt < 8; nt++) {
                o[g][nt][0] *= co0; o[g][nt][1] *= co0;
                o[g][nt][2] *= co1; o[g][nt][3] *= co1;
            }
            lacc[g][0] *= co0; lacc[g][1] *= co0;
            lacc[g][2] *= co1; lacc[g][3] *= co1;
        }

        #pragma unroll
        for (int kt = 0; kt < 4; kt++) {
            uint32_t aP[2][4];
            #pragma unroll
            for (int g = 0; g < 2; g++) {
                aP[g][0] = pl[g][2 * kt];     aP[g][1] = ph[g][2 * kt];
                aP[g][2] = pl[g][2 * kt + 1]; aP[g][3] = ph[g][2 * kt + 1];
                mma_f16(lacc[g], aP[g], bOnes, bOnes);
            }
            #pragma unroll
            for (int dp = 0; dp < 4; dp++) {
                uint32_t r0, r1, r2, r3;
                uint32_t addr = vBase + (kt * 16 + tRow) * (KVP * 2) + (dp * 16 + tCol) * 2;
                LDSM_X4T(r0, r1, r2, r3, addr);
                #pragma unroll
                for (int g = 0; g < 2; g++) {
                    mma_f16(o[g][2 * dp],     aP[g], r0, r1);
                    mma_f16(o[g][2 * dp + 1], aP[g], r2, r3);
                }
            }
        }
        stage = (stage + 1) & 3;
    }

    #pragma unroll
    for (int g = 0; g < 2; g++) {
        float l0 = __shfl_sync(0xffffffffu, lacc[g][0], lane & 28);
        float l1 = __shfl_sync(0xffffffffu, lacc[g][2], lane & 28);
        int r0 = qb * 256 + warp * 32 + g * 16 + lr;
        int r1 = r0 + 8;
        float g0 = sg[((size_t)(b * SQ) + r0) * NH + h];
        float g1 = sg[((size_t)(b * SQ) + r1) * NH + h];
        float f0 = g0 / l0, f1 = g1 / l1;
        __half* o0 = att + ((size_t)(b * SQ) + r0) * DIM + h * HD;
        __half* o1 = att + ((size_t)(b * SQ) + r1) * DIM + h * HD;
        #pragma unroll
        for (int nt = 0; nt < 8; nt++) {
            int col = nt * 8 + 2 * lq;
            *(__half2*)(o0 + col) = __floats2half2_rn(o[g][nt][0] * f0, o[g][nt][1] * f0);
            *(__half2*)(o1 + col) = __floats2half2_rn(o[g][nt][2] * f1, o[g][nt][3] * f1);
        }
    }
}

// ---------------------------------------------------------------------------
// launch
// ---------------------------------------------------------------------------
extern "C" void kernel_launch(void* const* d_in, const int* in_sizes, int n_in,
                              void* d_out, int out_size)
{
    const float* x         = (const float*)d_in[0];
    const float* prenorm_w = (const float*)d_in[1];
    const float* qkv_w     = (const float*)d_in[2];
    const float* gate_w    = (const float*)d_in[3];
    const float* o_w       = (const float*)d_in[4];
    const float* q_norm_w  = (const float*)d_in[5];
    const float* k_norm_w  = (const float*)d_in[6];
    float* out = (float*)d_out;

    __half *p_xnh, *p_qkvh, *p_atth, *p_wfull, *p_o_wh;
    float *p_gate;
    cudaGetSymbolAddress((void**)&p_xnh,   g_xnh);
    cudaGetSymbolAddress((void**)&p_qkvh,  g_qkvh);
    cudaGetSymbolAddress((void**)&p_atth,  g_atth);
    cudaGetSymbolAddress((void**)&p_gate,  g_gate);
    cudaGetSymbolAddress((void**)&p_wfull, g_wfull);
    cudaGetSymbolAddress((void**)&p_o_wh,  g_o_wh);

    cudaFuncSetAttribute(hgemm_nt<1>, cudaFuncAttributeMaxDynamicSharedMemorySize, GSMEM);
    cudaFuncSetAttribute(hgemm_nt<2>, cudaFuncAttributeMaxDynamicSharedMemorySize, GSMEM);
    cudaFuncSetAttribute(attn_f16,    cudaFuncAttributeMaxDynamicSharedMemorySize, ASMEM);

    // 0+1) prenorm + weight convert (fused)
    pre_conv_kernel<<<ROWS + CV_BLK, 256>>>(
        x, prenorm_w, p_xnh, qkv_w, gate_w, o_w, p_wfull, p_o_wh);

    // 2) QKV + gate + q/k-norm fused GEMM: [4096,1024] x [3200,1024]^T
    hgemm_nt<2><<<dim3(NFULL / 128, ROWS / 128), 256, GSMEM>>>(
        p_xnh, p_wfull, nullptr, p_qkvh, p_gate, q_norm_w, k_norm_w, NFULL, DIM);

    // 3) attention: 256 q-rows per CTA, 4-stage pipeline
    attn_f16<<<dim3(SQ / 256, NH, BATCH), 256, ASMEM>>>(p_qkvh, p_gate, p_atth);

    // 4) O GEMM + residual
    hgemm_nt<1><<<dim3(DIM / 128, ROWS / 128), 256, GSMEM>>>(
        p_atth, p_o_wh, x, out, nullptr, nullptr, nullptr, DIM, DIM);
}